// round 6
// baseline (speedup 1.0000x reference)
#include <cuda_runtime.h>

// Problem constants (TimeSeriesRegister): x[B,S,F], W[D,F], b[D], register[R,D]
#define S_DIM 512
#define F_DIM 64
#define D_DIM 256
#define R_DIM 4096
#define T_DIM 16
#define MAXB  8192
#define TD    (T_DIM * D_DIM)   // 4096 floats per batch in out

// Scratch layout inside out[b*TD ...] (all overwritten by K3 at the end):
//   slot 15: xe[b][0..255]        at +3840
//   slot 14: pscore[0..31] +3584, pidx[0..31] +3616
//   slot 13 (b<16 only): regsq chunk at +3328
#define XE_OFF   3840
#define PS_OFF   3584
#define PI_OFF   3616
#define RSQ_OFF  3328

// K2 tiling (static smem <= 48KB, low register pressure)
#define BT   32            // b rows per block
#define RC   128           // register rows per block
#define KC   64            // k-chunk (floats)
#define NKC  (D_DIM / KC)  // 4 k-chunks
#define NRT  (R_DIM / RC)  // 32 r-tiles
#define RP   68            // padded row stride in floats (272B)

// ---------------- K0: reg_sq -> out slot 13 of b = r>>8 ----------------
__global__ void k_regsq(const float* __restrict__ reg, float* __restrict__ out) {
    int r = blockIdx.x;           // R_DIM blocks
    int t = threadIdx.x;          // 64 threads
    float4 v = ((const float4*)reg)[(size_t)r * (D_DIM / 4) + t];
    float s = v.x * v.x + v.y * v.y + v.z * v.z + v.w * v.w;
    #pragma unroll
    for (int off = 16; off; off >>= 1) s += __shfl_down_sync(0xffffffffu, s, off);
    __shared__ float sm2[2];
    if ((t & 31) == 0) sm2[t >> 5] = s;
    __syncthreads();
    if (t == 0) out[(size_t)(r >> 8) * TD + RSQ_OFF + (r & 255)] = sm2[0] + sm2[1];
}

// ---------------- K1: fused mean-pool + projection -> out slot 15 ----------------
__global__ __launch_bounds__(256) void k_meanproj(const float* __restrict__ x,
                                                  const float* __restrict__ W,
                                                  const float* __restrict__ bias,
                                                  float* __restrict__ out) {
    int b   = blockIdx.x;
    int tid = threadIdx.x;
    int f4  = tid & 15;           // 16 float4 columns cover F=64
    int sl  = tid >> 4;           // 16 s-lanes

    const float4* xr = (const float4*)(x + (size_t)b * S_DIM * F_DIM);
    float4 acc = make_float4(0.f, 0.f, 0.f, 0.f);
    for (int j = 0; j < S_DIM / 16; j++) {
        float4 v = xr[(size_t)(sl + 16 * j) * 16 + f4];
        acc.x += v.x; acc.y += v.y; acc.z += v.z; acc.w += v.w;
    }

    __shared__ float4 red[256];
    __shared__ float  mean_s[F_DIM];
    red[tid] = acc;
    __syncthreads();
    #pragma unroll
    for (int off = 128; off >= 16; off >>= 1) {
        if (tid < off) {
            float4 o = red[tid + off];
            float4 a = red[tid];
            a.x += o.x; a.y += o.y; a.z += o.z; a.w += o.w;
            red[tid] = a;
        }
        __syncthreads();
    }
    if (tid < 16) {
        const float inv = 1.0f / (float)S_DIM;
        float4 m = red[tid];
        mean_s[tid * 4 + 0] = m.x * inv;
        mean_s[tid * 4 + 1] = m.y * inv;
        mean_s[tid * 4 + 2] = m.z * inv;
        mean_s[tid * 4 + 3] = m.w * inv;
    }
    __syncthreads();

    // projection: thread d computes xe[b,d]
    int d = tid;
    float a = bias[d];
    const float4* W4 = (const float4*)W;
    #pragma unroll
    for (int f = 0; f < 16; f++) {
        float4 w = W4[(size_t)d * 16 + f];
        a += w.x * mean_s[4 * f + 0] + w.y * mean_s[4 * f + 1]
           + w.z * mean_s[4 * f + 2] + w.w * mean_s[4 * f + 3];
    }
    out[(size_t)b * TD + XE_OFF + d] = a;
}

// ---------------- K2: tiled score GEMM + per-tile argmin ----------------
// grid = (NRT, B/BT), 256 threads = 8 warps.
// Warp w covers b rows w*4..w*4+3; lane covers r = lane + 32*j, j=0..3.
// score = ||reg||^2 - 2*dot(xe, reg). Static smem 43.5KB, ~65 regs.
__global__ __launch_bounds__(256) void k_dist(float* __restrict__ out,
                                              const float* __restrict__ reg) {
    __shared__ float xe_s[BT][RP];    //  8,704 B
    __shared__ float reg_s[RC][RP];   // 34,816 B

    int b0  = blockIdx.y * BT;
    int r0  = blockIdx.x * RC;
    int tid = threadIdx.x;
    int wp  = tid >> 5;   // warp 0..7  -> b rows wp*4 + i
    int ln  = tid & 31;   // lane 0..31 -> r = ln + 32*j

    float acc[4][4];
    #pragma unroll
    for (int i = 0; i < 4; i++)
        #pragma unroll
        for (int j = 0; j < 4; j++) acc[i][j] = 0.f;

    for (int kc = 0; kc < NKC; kc++) {
        // load xe chunk: 32 rows x 16 float4 (xe row b lives at out[b*TD + XE_OFF])
        #pragma unroll
        for (int idx = tid; idx < BT * (KC / 4); idx += 256) {
            int row = idx >> 4, c4 = idx & 15;
            float4 v = ((const float4*)out)[(size_t)(b0 + row) * (TD / 4) + (XE_OFF / 4) + kc * 16 + c4];
            *(float4*)&xe_s[row][c4 * 4] = v;
        }
        // load reg chunk: 128 rows x 16 float4
        #pragma unroll
        for (int idx = tid; idx < RC * (KC / 4); idx += 256) {
            int row = idx >> 4, c4 = idx & 15;
            float4 v = ((const float4*)reg)[(size_t)(r0 + row) * 64 + kc * 16 + c4];
            *(float4*)&reg_s[row][c4 * 4] = v;
        }
        __syncthreads();

        for (int k4 = 0; k4 < KC / 4; k4++) {
            float4 av0 = *(const float4*)&xe_s[wp * 4 + 0][k4 * 4];
            float4 av1 = *(const float4*)&xe_s[wp * 4 + 1][k4 * 4];
            float4 av2 = *(const float4*)&xe_s[wp * 4 + 2][k4 * 4];
            float4 av3 = *(const float4*)&xe_s[wp * 4 + 3][k4 * 4];
            #pragma unroll
            for (int j = 0; j < 4; j++) {
                float4 bv = *(const float4*)&reg_s[ln + 32 * j][k4 * 4];
                acc[0][j] += av0.x * bv.x + av0.y * bv.y + av0.z * bv.z + av0.w * bv.w;
                acc[1][j] += av1.x * bv.x + av1.y * bv.y + av1.z * bv.z + av1.w * bv.w;
                acc[2][j] += av2.x * bv.x + av2.y * bv.y + av2.z * bv.z + av2.w * bv.w;
                acc[3][j] += av3.x * bv.x + av3.y * bv.y + av3.z * bv.z + av3.w * bv.w;
            }
        }
        __syncthreads();
    }

    // per-lane regsq for its 4 r's (stored by K0 in out slot 13 of b = r>>8)
    float rsq[4];
    #pragma unroll
    for (int j = 0; j < 4; j++) {
        int r = r0 + ln + 32 * j;
        rsq[j] = out[(size_t)(r >> 8) * TD + RSQ_OFF + (r & 255)];
    }

    // epilogue: per-lane argmin over 4 r's, then full-warp shuffle reduce
    #pragma unroll
    for (int i = 0; i < 4; i++) {
        float best = 3.4e38f;
        int bidx = 0x7fffffff;
        #pragma unroll
        for (int j = 0; j < 4; j++) {     // r ascending in j
            int r = r0 + ln + 32 * j;
            float score = rsq[j] - 2.0f * acc[i][j];
            if (score < best || (score == best && r < bidx)) { best = score; bidx = r; }
        }
        #pragma unroll
        for (int off = 16; off; off >>= 1) {
            float os = __shfl_down_sync(0xffffffffu, best, off);
            int   oi = __shfl_down_sync(0xffffffffu, bidx, off);
            if (os < best || (os == best && oi < bidx)) { best = os; bidx = oi; }
        }
        if (ln == 0) {
            size_t base = (size_t)(b0 + wp * 4 + i) * TD;
            out[base + PS_OFF + blockIdx.x] = best;
            ((int*)out)[base + PI_OFF + blockIdx.x] = bidx;
        }
    }
}

// ---------------- K3: merge partials, gather + tile output, smuggle loss ----------------
// grid = B blocks, 64 threads. Reads scratch from out, then overwrites out[b] fully,
// except out[b][0]=lossb, out[b][1]=bitcast(c) (patched by K6 after K5 reads them).
__global__ __launch_bounds__(64) void k_gather(const float* __restrict__ reg,
                                               float* __restrict__ out) {
    int b   = blockIdx.x;
    int tid = threadIdx.x;     // 64 threads; thread = one float4 column of D
    size_t base = (size_t)b * TD;
    __shared__ int s_idx;

    if (tid < 32) {
        float s = out[base + PS_OFF + tid];
        int  ix = ((const int*)out)[base + PI_OFF + tid];
        #pragma unroll
        for (int off = 16; off; off >>= 1) {
            float os = __shfl_down_sync(0xffffffffu, s, off);
            int   oi = __shfl_down_sync(0xffffffffu, ix, off);
            if (os < s || (os == s && oi < ix)) { s = os; ix = oi; }
        }
        if (tid == 0) s_idx = ix;
    }
    __syncthreads();

    int c = s_idx;
    float4 v = ((const float4*)reg)[(size_t)c * (D_DIM / 4) + tid];
    float4 e = ((const float4*)out)[base / 4 + XE_OFF / 4 + tid];
    float p = (e.x - v.x) * (e.x - v.x) + (e.y - v.y) * (e.y - v.y)
            + (e.z - v.z) * (e.z - v.z) + (e.w - v.w) * (e.w - v.w);

    #pragma unroll
    for (int off = 16; off; off >>= 1) p += __shfl_down_sync(0xffffffffu, p, off);
    __shared__ float sred[2];
    if ((tid & 31) == 0) sred[tid >> 5] = p;
    __syncthreads();

    float4* ob = (float4*)(out + base);
    #pragma unroll
    for (int t = 0; t < T_DIM; t++) {
        float4 w = v;
        if (t == 0 && tid == 0) {          // smuggle lossb and c in floats 0..1
            w.x = sred[0] + sred[1];
            w.y = __int_as_float(c);
        }
        ob[t * (D_DIM / 4) + tid] = w;
    }
}

// ---------------- K5: deterministic loss reduction (reads smuggled lossb) ------------
__global__ void k_loss(float* __restrict__ out, int B) {
    int tid = threadIdx.x;  // 256
    float s = 0.f;
    for (int k = tid; k < B; k += 256) s += out[(size_t)k * TD];
    __shared__ float sm[256];
    sm[tid] = s;
    __syncthreads();
    #pragma unroll
    for (int off = 128; off; off >>= 1) {
        if (tid < off) sm[tid] += sm[tid + off];
        __syncthreads();
    }
    if (tid == 0) out[(size_t)B * TD] = sm[0] / (float)B;
}

// ---------------- K6: patch smuggled slots back to selected[0..1] ----------------
__global__ void k_patch(const float* __restrict__ reg, float* __restrict__ out) {
    if (threadIdx.x == 0) {
        size_t base = (size_t)blockIdx.x * TD;
        int c = __float_as_int(out[base + 1]);
        out[base + 0] = reg[(size_t)c * D_DIM + 0];
        out[base + 1] = reg[(size_t)c * D_DIM + 1];
    }
}

// ---------------- launcher (kernel launches only) ----------------
extern "C" void kernel_launch(void* const* d_in, const int* in_sizes, int n_in,
                              void* d_out, int out_size) {
    const float* x    = (const float*)d_in[0];
    const float* W    = (const float*)d_in[1];
    const float* bias = (const float*)d_in[2];
    const float* reg  = (const float*)d_in[3];
    float* out = (float*)d_out;

    int B = in_sizes[0] / (S_DIM * F_DIM);
    if (B > MAXB) B = MAXB;

    k_regsq<<<R_DIM, 64>>>(reg, out);
    k_meanproj<<<B, 256>>>(x, W, bias, out);
    dim3 g2(NRT, B / BT);
    k_dist<<<g2, 256>>>(out, reg);
    k_gather<<<B, 64>>>(reg, out);

    long long xd = (long long)B * TD;
    if ((long long)out_size > xd) {
        k_loss<<<1, 256>>>(out, B);
    }
    k_patch<<<B, 32>>>(reg, out);
}

// round 7
// speedup vs baseline: 1.0282x; 1.0282x over previous
#include <cuda_runtime.h>

// Problem constants (TimeSeriesRegister): x[B,S,F], W[D,F], b[D], register[R,D]
#define S_DIM 512
#define F_DIM 64
#define D_DIM 256
#define R_DIM 4096
#define T_DIM 16
#define MAXB  8192
#define TD    (T_DIM * D_DIM)   // 4096 floats per batch in out

// Scratch layout inside out[b*TD ...] (all overwritten by K3 at the end):
//   slot 15: xe[b][0..255]        at +3840
//   slot 14: pscore[0..31] +3584, pidx[0..31] +3616
//   slot 13 (b<16 only): regsq chunk at +3328
#define XE_OFF   3840
#define PS_OFF   3584
#define PI_OFF   3616
#define RSQ_OFF  3328

// K2 tiling (static smem <= 48KB, low register pressure)
#define BT   32            // b rows per block
#define RC   128           // register rows per block
#define KC   64            // k-chunk (floats)
#define NKC  (D_DIM / KC)  // 4 k-chunks
#define NRT  (R_DIM / RC)  // 32 r-tiles
#define RP   68            // padded row stride in floats (272B; 68 mod 32 = 4 -> conflict-free)

// packed fp32x2 FMA (sm_100+): d = a*b + d lanewise on two packed floats
__device__ __forceinline__ void ffma2(unsigned long long &d,
                                      unsigned long long a,
                                      unsigned long long b) {
    asm("fma.rn.f32x2 %0, %1, %2, %0;" : "+l"(d) : "l"(a), "l"(b));
}
__device__ __forceinline__ float2 unpack2(unsigned long long v) {
    float2 r;
    asm("mov.b64 {%0, %1}, %2;" : "=f"(r.x), "=f"(r.y) : "l"(v));
    return r;
}

// ---------------- K0: reg_sq -> out slot 13 of b = r>>8 ----------------
__global__ void k_regsq(const float* __restrict__ reg, float* __restrict__ out) {
    int r = blockIdx.x;           // R_DIM blocks
    int t = threadIdx.x;          // 64 threads
    float4 v = ((const float4*)reg)[(size_t)r * (D_DIM / 4) + t];
    float s = v.x * v.x + v.y * v.y + v.z * v.z + v.w * v.w;
    #pragma unroll
    for (int off = 16; off; off >>= 1) s += __shfl_down_sync(0xffffffffu, s, off);
    __shared__ float sm2[2];
    if ((t & 31) == 0) sm2[t >> 5] = s;
    __syncthreads();
    if (t == 0) out[(size_t)(r >> 8) * TD + RSQ_OFF + (r & 255)] = sm2[0] + sm2[1];
}

// ---------------- K1: fused mean-pool + projection -> out slot 15 ----------------
__global__ __launch_bounds__(256) void k_meanproj(const float* __restrict__ x,
                                                  const float* __restrict__ W,
                                                  const float* __restrict__ bias,
                                                  float* __restrict__ out) {
    int b   = blockIdx.x;
    int tid = threadIdx.x;
    int f4  = tid & 15;           // 16 float4 columns cover F=64
    int sl  = tid >> 4;           // 16 s-lanes

    const float4* xr = (const float4*)(x + (size_t)b * S_DIM * F_DIM);
    float4 acc = make_float4(0.f, 0.f, 0.f, 0.f);
    #pragma unroll 4
    for (int j = 0; j < S_DIM / 16; j++) {
        float4 v = xr[(size_t)(sl + 16 * j) * 16 + f4];
        acc.x += v.x; acc.y += v.y; acc.z += v.z; acc.w += v.w;
    }

    __shared__ float4 red[256];
    __shared__ float  mean_s[F_DIM];
    red[tid] = acc;
    __syncthreads();
    #pragma unroll
    for (int off = 128; off >= 16; off >>= 1) {
        if (tid < off) {
            float4 o = red[tid + off];
            float4 a = red[tid];
            a.x += o.x; a.y += o.y; a.z += o.z; a.w += o.w;
            red[tid] = a;
        }
        __syncthreads();
    }
    if (tid < 16) {
        const float inv = 1.0f / (float)S_DIM;
        float4 m = red[tid];
        mean_s[tid * 4 + 0] = m.x * inv;
        mean_s[tid * 4 + 1] = m.y * inv;
        mean_s[tid * 4 + 2] = m.z * inv;
        mean_s[tid * 4 + 3] = m.w * inv;
    }
    __syncthreads();

    // projection: thread d computes xe[b,d]
    int d = tid;
    float a = bias[d];
    const float4* W4 = (const float4*)W;
    #pragma unroll
    for (int f = 0; f < 16; f++) {
        float4 w = W4[(size_t)d * 16 + f];
        a += w.x * mean_s[4 * f + 0] + w.y * mean_s[4 * f + 1]
           + w.z * mean_s[4 * f + 2] + w.w * mean_s[4 * f + 3];
    }
    out[(size_t)b * TD + XE_OFF + d] = a;
}

// ---------------- K2: tiled score GEMM + per-tile argmin (packed f32x2) ----------------
// grid = (NRT, B/BT), 256 threads = 8 warps.
// Warp w covers b rows w*4..w*4+3; lane covers r = lane + 32*j, j=0..3.
// score = ||reg||^2 - 2*dot(xe, reg). Static smem 43.5KB, ~90 regs.
__global__ __launch_bounds__(256) void k_dist(float* __restrict__ out,
                                              const float* __restrict__ reg) {
    __shared__ float xe_s[BT][RP];    //  8,704 B
    __shared__ float reg_s[RC][RP];   // 34,816 B

    int b0  = blockIdx.y * BT;
    int r0  = blockIdx.x * RC;
    int tid = threadIdx.x;
    int wp  = tid >> 5;   // warp 0..7  -> b rows wp*4 + i
    int ln  = tid & 31;   // lane 0..31 -> r = ln + 32*j

    unsigned long long acc[4][4];     // packed {even_sum, odd_sum}
    #pragma unroll
    for (int i = 0; i < 4; i++)
        #pragma unroll
        for (int j = 0; j < 4; j++) acc[i][j] = 0ULL;

    for (int kc = 0; kc < NKC; kc++) {
        // load xe chunk: 32 rows x 16 float4
        #pragma unroll
        for (int idx = tid; idx < BT * (KC / 4); idx += 256) {
            int row = idx >> 4, c4 = idx & 15;
            float4 v = ((const float4*)out)[(size_t)(b0 + row) * (TD / 4) + (XE_OFF / 4) + kc * 16 + c4];
            *(float4*)&xe_s[row][c4 * 4] = v;
        }
        // load reg chunk: 128 rows x 16 float4
        #pragma unroll
        for (int idx = tid; idx < RC * (KC / 4); idx += 256) {
            int row = idx >> 4, c4 = idx & 15;
            float4 v = ((const float4*)reg)[(size_t)(r0 + row) * 64 + kc * 16 + c4];
            *(float4*)&reg_s[row][c4 * 4] = v;
        }
        __syncthreads();

        for (int k4 = 0; k4 < KC / 4; k4++) {
            ulonglong2 av[4];
            #pragma unroll
            for (int i = 0; i < 4; i++)
                av[i] = *(const ulonglong2*)&xe_s[wp * 4 + i][k4 * 4];
            #pragma unroll
            for (int j = 0; j < 4; j++) {
                ulonglong2 bv = *(const ulonglong2*)&reg_s[ln + 32 * j][k4 * 4];
                #pragma unroll
                for (int i = 0; i < 4; i++) {
                    ffma2(acc[i][j], av[i].x, bv.x);
                    ffma2(acc[i][j], av[i].y, bv.y);
                }
            }
        }
        __syncthreads();
    }

    // per-lane regsq for its 4 r's (stored by K0 in out slot 13 of b = r>>8)
    float rsq[4];
    #pragma unroll
    for (int j = 0; j < 4; j++) {
        int r = r0 + ln + 32 * j;
        rsq[j] = out[(size_t)(r >> 8) * TD + RSQ_OFF + (r & 255)];
    }

    // epilogue: per-lane argmin over 4 r's, then full-warp shuffle reduce
    #pragma unroll
    for (int i = 0; i < 4; i++) {
        float best = 3.4e38f;
        int bidx = 0x7fffffff;
        #pragma unroll
        for (int j = 0; j < 4; j++) {     // r ascending in j
            int r = r0 + ln + 32 * j;
            float2 p = unpack2(acc[i][j]);
            float score = rsq[j] - 2.0f * (p.x + p.y);
            if (score < best || (score == best && r < bidx)) { best = score; bidx = r; }
        }
        #pragma unroll
        for (int off = 16; off; off >>= 1) {
            float os = __shfl_down_sync(0xffffffffu, best, off);
            int   oi = __shfl_down_sync(0xffffffffu, bidx, off);
            if (os < best || (os == best && oi < bidx)) { best = os; bidx = oi; }
        }
        if (ln == 0) {
            size_t base = (size_t)(b0 + wp * 4 + i) * TD;
            out[base + PS_OFF + blockIdx.x] = best;
            ((int*)out)[base + PI_OFF + blockIdx.x] = bidx;
        }
    }
}

// ---------------- K3: merge partials, gather + tile output, smuggle loss ----------------
// grid = B blocks, 64 threads. Reads scratch from out, then overwrites out[b] fully,
// except out[b][0]=lossb, out[b][1]=bitcast(c) (patched by K6 after K5 reads them).
__global__ __launch_bounds__(64) void k_gather(const float* __restrict__ reg,
                                               float* __restrict__ out) {
    int b   = blockIdx.x;
    int tid = threadIdx.x;     // 64 threads; thread = one float4 column of D
    size_t base = (size_t)b * TD;
    __shared__ int s_idx;

    if (tid < 32) {
        float s = out[base + PS_OFF + tid];
        int  ix = ((const int*)out)[base + PI_OFF + tid];
        #pragma unroll
        for (int off = 16; off; off >>= 1) {
            float os = __shfl_down_sync(0xffffffffu, s, off);
            int   oi = __shfl_down_sync(0xffffffffu, ix, off);
            if (os < s || (os == s && oi < ix)) { s = os; ix = oi; }
        }
        if (tid == 0) s_idx = ix;
    }
    __syncthreads();

    int c = s_idx;
    float4 v = ((const float4*)reg)[(size_t)c * (D_DIM / 4) + tid];
    float4 e = ((const float4*)out)[base / 4 + XE_OFF / 4 + tid];
    float p = (e.x - v.x) * (e.x - v.x) + (e.y - v.y) * (e.y - v.y)
            + (e.z - v.z) * (e.z - v.z) + (e.w - v.w) * (e.w - v.w);

    #pragma unroll
    for (int off = 16; off; off >>= 1) p += __shfl_down_sync(0xffffffffu, p, off);
    __shared__ float sred[2];
    if ((tid & 31) == 0) sred[tid >> 5] = p;
    __syncthreads();

    float4* ob = (float4*)(out + base);
    #pragma unroll
    for (int t = 0; t < T_DIM; t++) {
        float4 w = v;
        if (t == 0 && tid == 0) {          // smuggle lossb and c in floats 0..1
            w.x = sred[0] + sred[1];
            w.y = __int_as_float(c);
        }
        ob[t * (D_DIM / 4) + tid] = w;
    }
}

// ---------------- K5: deterministic loss reduction (reads smuggled lossb) ------------
__global__ void k_loss(float* __restrict__ out, int B) {
    int tid = threadIdx.x;  // 256
    float s = 0.f;
    for (int k = tid; k < B; k += 256) s += out[(size_t)k * TD];
    __shared__ float sm[256];
    sm[tid] = s;
    __syncthreads();
    #pragma unroll
    for (int off = 128; off; off >>= 1) {
        if (tid < off) sm[tid] += sm[tid + off];
        __syncthreads();
    }
    if (tid == 0) out[(size_t)B * TD] = sm[0] / (float)B;
}

// ---------------- K6: patch smuggled slots back to selected[0..1] ----------------
__global__ void k_patch(const float* __restrict__ reg, float* __restrict__ out) {
    if (threadIdx.x == 0) {
        size_t base = (size_t)blockIdx.x * TD;
        int c = __float_as_int(out[base + 1]);
        out[base + 0] = reg[(size_t)c * D_DIM + 0];
        out[base + 1] = reg[(size_t)c * D_DIM + 1];
    }
}

// ---------------- launcher (kernel launches only) ----------------
extern "C" void kernel_launch(void* const* d_in, const int* in_sizes, int n_in,
                              void* d_out, int out_size) {
    const float* x    = (const float*)d_in[0];
    const float* W    = (const float*)d_in[1];
    const float* bias = (const float*)d_in[2];
    const float* reg  = (const float*)d_in[3];
    float* out = (float*)d_out;

    int B = in_sizes[0] / (S_DIM * F_DIM);
    if (B > MAXB) B = MAXB;

    k_regsq<<<R_DIM, 64>>>(reg, out);
    k_meanproj<<<B, 256>>>(x, W, bias, out);
    dim3 g2(NRT, B / BT);
    k_dist<<<g2, 256>>>(out, reg);
    k_gather<<<B, 64>>>(reg, out);

    long long xd = (long long)B * TD;
    if ((long long)out_size > xd) {
        k_loss<<<1, 256>>>(out, B);
    }
    k_patch<<<B, 32>>>(reg, out);
}

// round 8
// speedup vs baseline: 1.3831x; 1.3452x over previous
#include <cuda_runtime.h>

// Problem constants (TimeSeriesRegister): x[B,S,F], W[D,F], b[D], register[R,D]
#define S_DIM 512
#define F_DIM 64
#define D_DIM 256
#define R_DIM 4096
#define T_DIM 16
#define MAXB  8192
#define TD    (T_DIM * D_DIM)   // 4096 floats per batch in out

// Scratch layout inside out[b*TD ...] (all overwritten by K3 at the end):
//   slot 15: xe[b][0..255]        at +3840
//   slot 14: pscore[0..31] +3584, pidx[0..31] +3616
//   slot 13 (b<16 only): regsq chunk at +3328
#define XE_OFF   3840
#define PS_OFF   3584
#define PI_OFF   3616
#define RSQ_OFF  3328

// k_dist tiling (tensor-core 3xTF32)
#define DBT  64            // CTA m tile (b rows)
#define DRC  128           // CTA n tile (register rows)
#define DKC  32            // k chunk (floats)
#define DNRT (R_DIM / DRC) // 32 r-tiles
#define DRP  36            // padded row stride in floats

// ---- tf32 helpers ----
__device__ __forceinline__ unsigned tf32_bits(float x) {
    unsigned u;
    asm("cvt.rna.tf32.f32 %0, %1;" : "=r"(u) : "f"(x));
    return u;
}
__device__ __forceinline__ float tf32_val(float x) {
    return __uint_as_float(tf32_bits(x));
}
// D(c[4]) += A(a0..a3) * B(b0,b1), m16n8k8 tf32
__device__ __forceinline__ void mma_tf32(float c[4],
                                         unsigned a0, unsigned a1, unsigned a2, unsigned a3,
                                         unsigned b0, unsigned b1) {
    asm volatile(
        "mma.sync.aligned.m16n8k8.row.col.f32.tf32.tf32.f32 "
        "{%0,%1,%2,%3}, {%4,%5,%6,%7}, {%8,%9}, {%0,%1,%2,%3};"
        : "+f"(c[0]), "+f"(c[1]), "+f"(c[2]), "+f"(c[3])
        : "r"(a0), "r"(a1), "r"(a2), "r"(a3), "r"(b0), "r"(b1));
}

// ---------------- K0: reg_sq -> out slot 13 of b = r>>8 ----------------
__global__ void k_regsq(const float* __restrict__ reg, float* __restrict__ out) {
    int r = blockIdx.x;           // R_DIM blocks
    int t = threadIdx.x;          // 64 threads
    float4 v = ((const float4*)reg)[(size_t)r * (D_DIM / 4) + t];
    float s = v.x * v.x + v.y * v.y + v.z * v.z + v.w * v.w;
    #pragma unroll
    for (int off = 16; off; off >>= 1) s += __shfl_down_sync(0xffffffffu, s, off);
    __shared__ float sm2[2];
    if ((t & 31) == 0) sm2[t >> 5] = s;
    __syncthreads();
    if (t == 0) out[(size_t)(r >> 8) * TD + RSQ_OFF + (r & 255)] = sm2[0] + sm2[1];
}

// ---------------- K1: fused mean-pool + projection -> out slot 15 ----------------
__global__ __launch_bounds__(256) void k_meanproj(const float* __restrict__ x,
                                                  const float* __restrict__ W,
                                                  const float* __restrict__ bias,
                                                  float* __restrict__ out) {
    int b   = blockIdx.x;
    int tid = threadIdx.x;
    int f4  = tid & 15;           // 16 float4 columns cover F=64
    int sl  = tid >> 4;           // 16 s-lanes

    const float4* xr = (const float4*)(x + (size_t)b * S_DIM * F_DIM);
    float4 acc = make_float4(0.f, 0.f, 0.f, 0.f);
    #pragma unroll 4
    for (int j = 0; j < S_DIM / 16; j++) {
        float4 v = xr[(size_t)(sl + 16 * j) * 16 + f4];
        acc.x += v.x; acc.y += v.y; acc.z += v.z; acc.w += v.w;
    }

    __shared__ float4 red[256];
    __shared__ float  mean_s[F_DIM];
    red[tid] = acc;
    __syncthreads();
    #pragma unroll
    for (int off = 128; off >= 16; off >>= 1) {
        if (tid < off) {
            float4 o = red[tid + off];
            float4 a = red[tid];
            a.x += o.x; a.y += o.y; a.z += o.z; a.w += o.w;
            red[tid] = a;
        }
        __syncthreads();
    }
    if (tid < 16) {
        const float inv = 1.0f / (float)S_DIM;
        float4 m = red[tid];
        mean_s[tid * 4 + 0] = m.x * inv;
        mean_s[tid * 4 + 1] = m.y * inv;
        mean_s[tid * 4 + 2] = m.z * inv;
        mean_s[tid * 4 + 3] = m.w * inv;
    }
    __syncthreads();

    // projection: thread d computes xe[b,d]
    int d = tid;
    float a = bias[d];
    const float4* W4 = (const float4*)W;
    #pragma unroll
    for (int f = 0; f < 16; f++) {
        float4 w = W4[(size_t)d * 16 + f];
        a += w.x * mean_s[4 * f + 0] + w.y * mean_s[4 * f + 1]
           + w.z * mean_s[4 * f + 2] + w.w * mean_s[4 * f + 3];
    }
    out[(size_t)b * TD + XE_OFF + d] = a;
}

// ---------------- K2: 3xTF32 tensor-core score GEMM + per-tile argmin ----------------
// grid = (DNRT, B/DBT), 256 threads = 8 warps = 4(m) x 2(n).
// Warp tile: m16 x n64 (8 n-subtiles of m16n8k8). score = ||reg||^2 - 2*dot(xe,reg).
__global__ __launch_bounds__(256) void k_dist(float* __restrict__ out,
                                              const float* __restrict__ reg) {
    __shared__ float xe_s[DBT][DRP];    // fp32 xe chunk (split per-fragment)
    __shared__ float rh_s[DRC][DRP];    // reg tf32-hi
    __shared__ float rl_s[DRC][DRP];    // reg tf32-lo (residual)
    __shared__ float ps_part[4][16][2];
    __shared__ int   pi_part[4][16][2];

    int b0  = blockIdx.y * DBT;
    int r0  = blockIdx.x * DRC;
    int tid = threadIdx.x;
    int wid = tid >> 5, ln = tid & 31;
    int wm  = wid & 3;        // m-warp: rows wm*16 .. +15
    int wn  = wid >> 2;       // n-warp: cols wn*64 .. +63
    int qr  = ln >> 2;        // 0..7
    int qc  = ln & 3;         // 0..3

    float acc[8][4];
    #pragma unroll
    for (int t = 0; t < 8; t++)
        #pragma unroll
        for (int i = 0; i < 4; i++) acc[t][i] = 0.f;

    for (int kc = 0; kc < D_DIM / DKC; kc++) {
        // load xe chunk: 64 rows x 8 float4 (fp32)
        #pragma unroll
        for (int i = tid; i < DBT * 8; i += 256) {
            int row = i >> 3, c = i & 7;
            float4 v = ((const float4*)out)[(size_t)(b0 + row) * (TD / 4) + (XE_OFF / 4) + kc * 8 + c];
            *(float4*)&xe_s[row][c * 4] = v;
        }
        // load + split reg chunk: 128 rows x 8 float4
        #pragma unroll
        for (int i = tid; i < DRC * 8; i += 256) {
            int row = i >> 3, c = i & 7;
            float4 v = ((const float4*)reg)[(size_t)(r0 + row) * 64 + kc * 8 + c];
            float4 h, l;
            h.x = tf32_val(v.x); l.x = v.x - h.x;
            h.y = tf32_val(v.y); l.y = v.y - h.y;
            h.z = tf32_val(v.z); l.z = v.z - h.z;
            h.w = tf32_val(v.w); l.w = v.w - h.w;
            *(float4*)&rh_s[row][c * 4] = h;
            *(float4*)&rl_s[row][c * 4] = l;
        }
        __syncthreads();

        #pragma unroll
        for (int k8 = 0; k8 < DKC / 8; k8++) {
            int k0 = k8 * 8 + qc;
            // A fragment (fp32 -> hi/lo split in registers)
            float a0f = xe_s[wm * 16 + qr    ][k0];
            float a1f = xe_s[wm * 16 + qr + 8][k0];
            float a2f = xe_s[wm * 16 + qr    ][k0 + 4];
            float a3f = xe_s[wm * 16 + qr + 8][k0 + 4];
            unsigned ah0 = tf32_bits(a0f), ah1 = tf32_bits(a1f);
            unsigned ah2 = tf32_bits(a2f), ah3 = tf32_bits(a3f);
            unsigned al0 = tf32_bits(a0f - __uint_as_float(ah0));
            unsigned al1 = tf32_bits(a1f - __uint_as_float(ah1));
            unsigned al2 = tf32_bits(a2f - __uint_as_float(ah2));
            unsigned al3 = tf32_bits(a3f - __uint_as_float(ah3));

            #pragma unroll
            for (int t = 0; t < 8; t++) {
                int nb = wn * 64 + t * 8 + qr;
                unsigned bh0 = __float_as_uint(rh_s[nb][k8 * 8 + qc]);
                unsigned bh1 = __float_as_uint(rh_s[nb][k8 * 8 + qc + 4]);
                unsigned bl0 = __float_as_uint(rl_s[nb][k8 * 8 + qc]);
                unsigned bl1 = __float_as_uint(rl_s[nb][k8 * 8 + qc + 4]);
                mma_tf32(acc[t], ah0, ah1, ah2, ah3, bh0, bh1);   // hi*hi
                mma_tf32(acc[t], ah0, ah1, ah2, ah3, bl0, bl1);   // hi*lo
                mma_tf32(acc[t], al0, al1, al2, al3, bh0, bh1);   // lo*hi
            }
        }
        __syncthreads();
    }

    // regsq tile into smem (reuse xe_s storage)
    float* rs = &xe_s[0][0];
    if (tid < DRC) {
        int r = r0 + tid;
        rs[tid] = out[(size_t)(r >> 8) * TD + RSQ_OFF + (r & 255)];
    }
    __syncthreads();

    // epilogue: argmin. D rows handled by this thread: wm*16+qr and +8.
    #pragma unroll
    for (int rsel = 0; rsel < 2; rsel++) {
        float best = 3.4e38f;
        int bidx = 0x7fffffff;
        #pragma unroll
        for (int t = 0; t < 8; t++) {
            #pragma unroll
            for (int cc = 0; cc < 2; cc++) {
                int rl_ = wn * 64 + t * 8 + 2 * qc + cc;
                float sc = rs[rl_] - 2.0f * acc[t][rsel * 2 + cc];
                int r = r0 + rl_;
                if (sc < best || (sc == best && r < bidx)) { best = sc; bidx = r; }
            }
        }
        // reduce across the 4 lanes (qc) sharing the same row
        #pragma unroll
        for (int m = 1; m <= 2; m <<= 1) {
            float os = __shfl_xor_sync(0xffffffffu, best, m);
            int   oi = __shfl_xor_sync(0xffffffffu, bidx, m);
            if (os < best || (os == best && oi < bidx)) { best = os; bidx = oi; }
        }
        if (qc == 0) {
            int mrow = qr + rsel * 8;   // 0..15 within warp m-tile
            ps_part[wm][mrow][wn] = best;
            pi_part[wm][mrow][wn] = bidx;
        }
    }
    __syncthreads();

    if (tid < 64) {
        int wmm = tid >> 4, mr = tid & 15;
        float s0 = ps_part[wmm][mr][0], s1 = ps_part[wmm][mr][1];
        int   i0 = pi_part[wmm][mr][0], i1 = pi_part[wmm][mr][1];
        float bs = s0; int bi = i0;
        if (s1 < bs || (s1 == bs && i1 < bi)) { bs = s1; bi = i1; }
        size_t base = (size_t)(b0 + wmm * 16 + mr) * TD;
        out[base + PS_OFF + blockIdx.x] = bs;
        ((int*)out)[base + PI_OFF + blockIdx.x] = bi;
    }
}

// ---------------- K3: merge partials, gather + tile output, smuggle loss ----------------
// grid = B blocks, 64 threads. Reads scratch from out, then overwrites out[b] fully,
// except out[b][0]=lossb, out[b][1]=bitcast(c) (patched by K6 after K5 reads them).
__global__ __launch_bounds__(64) void k_gather(const float* __restrict__ reg,
                                               float* __restrict__ out) {
    int b   = blockIdx.x;
    int tid = threadIdx.x;     // 64 threads; thread = one float4 column of D
    size_t base = (size_t)b * TD;
    __shared__ int s_idx;

    if (tid < 32) {
        float s = out[base + PS_OFF + tid];
        int  ix = ((const int*)out)[base + PI_OFF + tid];
        #pragma unroll
        for (int off = 16; off; off >>= 1) {
            float os = __shfl_down_sync(0xffffffffu, s, off);
            int   oi = __shfl_down_sync(0xffffffffu, ix, off);
            if (os < s || (os == s && oi < ix)) { s = os; ix = oi; }
        }
        if (tid == 0) s_idx = ix;
    }
    __syncthreads();

    int c = s_idx;
    float4 v = ((const float4*)reg)[(size_t)c * (D_DIM / 4) + tid];
    float4 e = ((const float4*)out)[base / 4 + XE_OFF / 4 + tid];
    float p = (e.x - v.x) * (e.x - v.x) + (e.y - v.y) * (e.y - v.y)
            + (e.z - v.z) * (e.z - v.z) + (e.w - v.w) * (e.w - v.w);

    #pragma unroll
    for (int off = 16; off; off >>= 1) p += __shfl_down_sync(0xffffffffu, p, off);
    __shared__ float sred[2];
    if ((tid & 31) == 0) sred[tid >> 5] = p;
    __syncthreads();

    float4* ob = (float4*)(out + base);
    #pragma unroll
    for (int t = 0; t < T_DIM; t++) {
        float4 w = v;
        if (t == 0 && tid == 0) {          // smuggle lossb and c in floats 0..1
            w.x = sred[0] + sred[1];
            w.y = __int_as_float(c);
        }
        ob[t * (D_DIM / 4) + tid] = w;
    }
}

// ---------------- K5: deterministic loss reduction (reads smuggled lossb) ------------
__global__ void k_loss(float* __restrict__ out, int B) {
    int tid = threadIdx.x;  // 256
    float s = 0.f;
    for (int k = tid; k < B; k += 256) s += out[(size_t)k * TD];
    __shared__ float sm[256];
    sm[tid] = s;
    __syncthreads();
    #pragma unroll
    for (int off = 128; off; off >>= 1) {
        if (tid < off) sm[tid] += sm[tid + off];
        __syncthreads();
    }
    if (tid == 0) out[(size_t)B * TD] = sm[0] / (float)B;
}

// ---------------- K6: patch smuggled slots back to selected[0..1] ----------------
__global__ void k_patch(const float* __restrict__ reg, float* __restrict__ out) {
    if (threadIdx.x == 0) {
        size_t base = (size_t)blockIdx.x * TD;
        int c = __float_as_int(out[base + 1]);
        out[base + 0] = reg[(size_t)c * D_DIM + 0];
        out[base + 1] = reg[(size_t)c * D_DIM + 1];
    }
}

// ---------------- launcher (kernel launches only) ----------------
extern "C" void kernel_launch(void* const* d_in, const int* in_sizes, int n_in,
                              void* d_out, int out_size) {
    const float* x    = (const float*)d_in[0];
    const float* W    = (const float*)d_in[1];
    const float* bias = (const float*)d_in[2];
    const float* reg  = (const float*)d_in[3];
    float* out = (float*)d_out;

    int B = in_sizes[0] / (S_DIM * F_DIM);
    if (B > MAXB) B = MAXB;

    k_regsq<<<R_DIM, 64>>>(reg, out);
    k_meanproj<<<B, 256>>>(x, W, bias, out);
    dim3 g2(DNRT, B / DBT);
    k_dist<<<g2, 256>>>(out, reg);
    k_gather<<<B, 64>>>(reg, out);

    long long xd = (long long)B * TD;
    if ((long long)out_size > xd) {
        k_loss<<<1, 256>>>(out, B);
    }
    k_patch<<<B, 32>>>(reg, out);
}